// round 16
// baseline (speedup 1.0000x reference)
#include <cuda_runtime.h>

#define H 512
#define LSEQ 1024
#define NROWS 4096
#define NST 64

typedef unsigned long long u64;

// ---- complex helpers ----
__device__ __forceinline__ float2 cmul(float2 a, float2 b) {
    return make_float2(a.x*b.x - a.y*b.y, a.x*b.y + a.y*b.x);
}
__device__ __forceinline__ float2 cadd(float2 a, float2 b) { return make_float2(a.x+b.x, a.y+b.y); }
__device__ __forceinline__ float2 csub(float2 a, float2 b) { return make_float2(a.x-b.x, a.y-b.y); }
__device__ __forceinline__ float2 cscale(float2 a, float s) { return make_float2(a.x*s, a.y*s); }
__device__ __forceinline__ float2 cinv(float2 d) {
    float inv = 1.f / (d.x*d.x + d.y*d.y);
    return make_float2(d.x*inv, -d.y*inv);
}

// ---- tf32 ----
__device__ __forceinline__ unsigned f2tf(float x) {
    unsigned u; asm("cvt.rna.tf32.f32 %0,%1;" : "=r"(u) : "f"(x)); return u;
}
__device__ __forceinline__ void mma_tf32(float* c, const unsigned* a, const unsigned* b) {
    asm("mma.sync.aligned.m16n8k8.row.col.f32.tf32.tf32.f32 "
        "{%0,%1,%2,%3}, {%4,%5,%6,%7}, {%8,%9}, {%0,%1,%2,%3};"
        : "+f"(c[0]), "+f"(c[1]), "+f"(c[2]), "+f"(c[3])
        : "r"(a[0]), "r"(a[1]), "r"(a[2]), "r"(a[3]), "r"(b[0]), "r"(b[1]));
}

__device__ __forceinline__ float gelu1(float y) {
    float z = 0.7978845608f * (y + 0.044715f * y * y * y);
    return y / (1.f + __expf(-2.f * z));
}

// ---- scratch ----
__device__ float  g_xn[NROWS * H];
__device__ float  g_yg[NROWS * H];
__device__ float  g_part[8][NROWS * H];
__device__ float2 g_M[2][NST * NST];
__device__ float2 g_MT[2][NST * NST];
__device__ float2 g_S[NST * NST];
__device__ float  g_K[LSEQ];
__device__ unsigned g_cnt[128];   // per-output-tile counters: (b*4+hT)*8+tT (zero-init)

// ---- reduce over threads 0..63 (others pass zero; all 256 call) ----
__device__ __forceinline__ float2 reduce64b(float2 val, float2* red) {
    int t = threadIdx.x;
#pragma unroll
    for (int o = 16; o > 0; o >>= 1) {
        val.x += __shfl_down_sync(0xffffffffu, val.x, o);
        val.y += __shfl_down_sync(0xffffffffu, val.y, o);
    }
    if (t < 64 && (t & 31) == 0) red[t >> 5] = val;
    __syncthreads();
    float2 r = cadd(red[0], red[1]);
    __syncthreads();
    return r;
}

// ================= sq0: fused setup + first squaring (grid 65) =================
__global__ void __launch_bounds__(256) k_sq0(
    const float* lre, const float* lim, const float* pre, const float* pim,
    const float* bre, const float* bim, const float* logstep) {
    __shared__ float2 AbS[NST * 65];
    __shared__ float2 su[NST], sv[NST], sg[NST], ss0[NST];
    __shared__ float2 vec[NST];
    __shared__ float2 part[3][NST];
    __shared__ float2 red[2];
    int tid = threadIdx.x, blk = blockIdx.x;
    const float2 zero = make_float2(0.f, 0.f);

    {
        float dt = expf(logstep[0]);
        float w0 = 2.f / dt;
        float2 lam = zero, p = zero, bb = zero, Dl = zero, d0 = zero, sp = zero;
        if (tid < NST) {
            lam = make_float2(lre[tid], lim[tid]);
            p   = make_float2(pre[tid], pim[tid]);
            bb  = make_float2(bre[tid], bim[tid]);
            Dl  = cinv(make_float2(w0 - lam.x, -lam.y));
            d0  = make_float2(w0 + lam.x, lam.y);
            sp  = cscale(Dl, p.x*p.x + p.y*p.y);
        }
        float2 sig = reduce64b(sp, red);
        float2 Db = zero, tp = zero;
        if (tid < NST) {
            Db = cmul(Dl, bb);
            tp = cmul(make_float2(p.x, -p.y), Db);
        }
        float2 tau = reduce64b(tp, red);
        if (tid < NST) {
            float2 alpha = cinv(make_float2(1.f + sig.x, sig.y));
            float2 uu = cmul(Dl, p);
            float2 gg = cmul(Dl, d0);
            float2 as = cmul(alpha, sig);
            float2 coef = csub(make_float2(as.x - 1.f, as.y), cmul(alpha, gg));
            float2 vv = cmul(make_float2(p.x, -p.y), coef);
            float2 Bv = cscale(csub(Db, cmul(cmul(alpha, tau), uu)), 2.f);
            su[tid] = uu; sv[tid] = vv; sg[tid] = gg; ss0[tid] = Bv;
        }
        __syncthreads();
        for (int idx = tid; idx < 4096; idx += 256) {
            int i = idx >> 6, j = idx & 63;
            float2 e = cmul(su[i], sv[j]);
            if (i == j) e = cadd(e, sg[i]);
            AbS[i * 65 + j] = e;
        }
        __syncthreads();
    }

    if (blk < 64) {
        if (tid < NST) vec[tid] = AbS[blk * 65 + tid];
        __syncthreads();
        int j = tid & 63, q = tid >> 6;
        float2 acc = zero;
#pragma unroll
        for (int nn = 0; nn < 16; nn++) {
            int n = q * 16 + nn;
            acc = cadd(acc, cmul(vec[n], AbS[n * 65 + j]));
        }
        if (q) part[q - 1][j] = acc;
        __syncthreads();
        if (q == 0) {
            acc = cadd(acc, cadd(part[0][j], cadd(part[1][j], part[2][j])));
            g_M[0][blk * NST + j] = acc;
            g_MT[0][j * NST + blk] = acc;
        }
    } else {
        float2 dp = zero;
        if (tid < NST) dp = cmul(sv[tid], ss0[tid]);
        float2 dot = reduce64b(dp, red);
        if (tid < NST) {
            g_S[tid] = ss0[tid];
            g_S[NST + tid] = cadd(cmul(sg[tid], ss0[tid]), cmul(su[tid], dot));
        }
    }
}

// ================= sqN: phase ph in 1..5 (grid 64 + 2^ph) =================
__global__ void __launch_bounds__(256) k_sqN(int ph) {
    const float2* Min  = g_M[(ph + 1) & 1];
    const float2* MinT = g_MT[(ph + 1) & 1];
    float2* Mout  = g_M[ph & 1];
    float2* MoutT = g_MT[ph & 1];
    __shared__ float2 vec[NST];
    __shared__ float2 part[3][NST];
    int blk = blockIdx.x, tid = threadIdx.x;
    int j = tid & 63, q = tid >> 6;
    const float2 zero = make_float2(0.f, 0.f);
    if (blk < 64) {
        if (tid < NST) vec[tid] = Min[blk * NST + tid];
        __syncthreads();
        float2 acc = zero;
#pragma unroll
        for (int nn = 0; nn < 16; nn++) {
            int n = q * 16 + nn;
            acc = cadd(acc, cmul(vec[n], Min[n * NST + j]));
        }
        if (q) part[q - 1][j] = acc;
        __syncthreads();
        if (q == 0) {
            acc = cadd(acc, cadd(part[0][j], cadd(part[1][j], part[2][j])));
            Mout[blk * NST + j] = acc;
            MoutT[j * NST + blk] = acc;
        }
    } else {
        int r = 1 << ph;
        int k = blk - 64;
        if (tid < NST) vec[tid] = g_S[k * NST + tid];
        __syncthreads();
        float2 acc = zero;
#pragma unroll
        for (int nn = 0; nn < 16; nn++) {
            int n = q * 16 + nn;
            acc = cadd(acc, cmul(vec[n], MinT[n * NST + j]));
        }
        if (q) part[q - 1][j] = acc;
        __syncthreads();
        if (q == 0) {
            acc = cadd(acc, cadd(part[0][j], cadd(part[1][j], part[2][j])));
            g_S[(k + r) * NST + j] = acc;
        }
    }
}

// ================= ktail + LayerNorm fused (grid 1 + 512, 1024 thr) =================
#define KT_SMEM_F2 (4160 + 4160 + 1024 + 64 + 64)
__global__ void __launch_bounds__(1024, 1) k_ktail_ln(
    const float* cre, const float* cim,
    const float* __restrict__ x, const float* __restrict__ w,
    const float* __restrict__ bi) {
    extern __shared__ float2 sm[];
    int tid = threadIdx.x, blk = blockIdx.x;

    if (blk > 0) {
        // ---- LayerNorm: 8 rows per block, 128 threads per row ----
        __shared__ float rs[8][4], rss[8][4];
        int grp = tid >> 7;
        int t = tid & 127;
        int row = (blk - 1) * 8 + grp;
        float4 v = ((const float4*)(x + (size_t)row * H))[t];
        float s  = v.x + v.y + v.z + v.w;
        float ss = v.x*v.x + v.y*v.y + v.z*v.z + v.w*v.w;
#pragma unroll
        for (int o = 16; o > 0; o >>= 1) {
            s  += __shfl_down_sync(0xffffffffu, s, o);
            ss += __shfl_down_sync(0xffffffffu, ss, o);
        }
        if ((t & 31) == 0) { rs[grp][t >> 5] = s; rss[grp][t >> 5] = ss; }
        __syncthreads();
        float sum = rs[grp][0] + rs[grp][1] + rs[grp][2] + rs[grp][3];
        float sq  = rss[grp][0] + rss[grp][1] + rss[grp][2] + rss[grp][3];
        float mu = sum * (1.f / H);
        float var = sq * (1.f / H) - mu * mu;
        float rstd = rsqrtf(var + 1e-5f);
        float4 wv = ((const float4*)w)[t];
        float4 bv = ((const float4*)bi)[t];
        float4 o;
        o.x = (v.x - mu) * rstd * wv.x + bv.x;
        o.y = (v.y - mu) * rstd * wv.y + bv.y;
        o.z = (v.z - mu) * rstd * wv.z + bv.z;
        o.w = (v.w - mu) * rstd * wv.w + bv.w;
        ((float4*)(g_xn + (size_t)row * H))[t] = o;
        return;
    }

    // ---- block 0: ktail ----
    float2* ST = sm;
    float2* Ms = ST + 4160;
    float2* Rm = Ms + 4160;
    float2* Rc = Rm + 1024;
    float2* Rn = Rc + 64;
    const float2 zero = make_float2(0.f, 0.f);
    for (int e = tid; e < NST * NST; e += 1024) {
        int k = e >> 6, n = e & 63;
        ST[n * 65 + k] = g_S[e];
        Ms[k * 65 + n] = g_M[1][e];   // Ab^64 (phase-5 output)
    }
    if (tid < NST) Rc[tid] = make_float2(cre[tid], cim[tid]);
    __syncthreads();
    int i = tid >> 4, q = tid & 15;
    for (int m = 0; m < 16; m++) {
        if (tid < NST) Rm[m * NST + tid] = Rc[tid];
        float2 acc = zero;
#pragma unroll
        for (int nn = 0; nn < 4; nn++) {
            int n = q * 4 + nn;
            acc = cadd(acc, cmul(Rc[n], Ms[n * 65 + i]));
        }
#pragma unroll
        for (int o = 8; o > 0; o >>= 1) {
            acc.x += __shfl_down_sync(0xffffffffu, acc.x, o, 16);
            acc.y += __shfl_down_sync(0xffffffffu, acc.y, o, 16);
        }
        if (q == 0) Rn[i] = acc;
        __syncthreads();
        if (tid < NST) Rc[tid] = Rn[tid];
        __syncthreads();
    }
    int m = tid >> 6, k = tid & 63;
    float acc = 0.f;
#pragma unroll 8
    for (int n = 0; n < NST; n++) {
        float2 a = Rm[m * NST + n];
        float2 s = ST[n * 65 + k];
        acc += a.x * s.x - a.y * s.y;
    }
    g_K[m * NST + k] = acc;
}

// ================= conv (tf32 TC) + fused last-block reduce + GELU =================
#define CONV_SMEM 103488

__global__ void __launch_bounds__(256) k_conv(const float* __restrict__ dscale) {
    extern __shared__ char cvs[];
    float* Ks = (float*)cvs;
    unsigned* Ts = (unsigned*)(cvs + 1088);
    unsigned* Xs = (unsigned*)(cvs + 68672);
    __shared__ unsigned s_last;

    int idx = blockIdx.x;
    int b = idx / 144;
    int rem = idx - b * 144;
    int hT = rem / 36;
    int pr = rem - hT * 36;
    int tT = 0;
    while ((tT + 1) * (tT + 2) / 2 <= pr) tT++;
    int sT = pr - tT * (tT + 1) / 2;
    int t0 = tT * 128, s0 = sT * 128, h0 = hT * 128;
    int D0 = t0 - s0;

    int tid = threadIdx.x;
    int lane = tid & 31, warp = tid >> 5;
    int g = lane >> 2, t = lane & 3;
    int wm = warp & 3, wn = warp >> 2;

    for (int jj = tid; jj < 264; jj += 256) {
        int d = D0 + jj - 131;
        Ks[jj] = (d >= 0 && d < LSEQ) ? g_K[d] : 0.f;
    }
    __syncthreads();

    {
        int tt = tid >> 1, sbase = (tid & 1) * 64;
        const float* kp = Ks + 131 + tt - sbase;
        unsigned* dst = Ts + tt * 132 + sbase;
#pragma unroll
        for (int s = 0; s < 64; s += 4) {
            uint4 v = make_uint4(f2tf(kp[-s]), f2tf(kp[-s - 1]),
                                 f2tf(kp[-s - 2]), f2tf(kp[-s - 3]));
            *(uint4*)(dst + s) = v;
        }
    }

    int hq = tid & 31, sr0 = tid >> 5;
    const float* Xg = g_xn + (size_t)(b * LSEQ + s0) * H + h0 + 4 * hq;
    float4 st[4];
#pragma unroll
    for (int i2 = 0; i2 < 4; i2++) st[i2] = *(const float4*)(Xg + (size_t)(sr0 + 8 * i2) * H);
#pragma unroll
    for (int i2 = 0; i2 < 4; i2++) {
        uint4 v = make_uint4(f2tf(st[i2].x), f2tf(st[i2].y), f2tf(st[i2].z), f2tf(st[i2].w));
        *(uint4*)(Xs + (sr0 + 8 * i2) * 136 + 4 * hq) = v;
    }
    __syncthreads();

    float C[2][8][4];
#pragma unroll
    for (int a = 0; a < 2; a++)
#pragma unroll
        for (int nb = 0; nb < 8; nb++)
#pragma unroll
            for (int cc = 0; cc < 4; cc++) C[a][nb][cc] = 0.f;

    for (int ch = 0; ch < 4; ch++) {
        if (ch < 3) {
#pragma unroll
            for (int i2 = 0; i2 < 4; i2++)
                st[i2] = *(const float4*)(Xg + (size_t)((ch + 1) * 32 + sr0 + 8 * i2) * H);
        }
        const unsigned* XB = Xs + (ch & 1) * 4352;
#pragma unroll
        for (int ks = 0; ks < 4; ks++) {
            int kkA = ch * 32 + ks * 8 + t;
            unsigned af[2][4];
#pragma unroll
            for (int mt = 0; mt < 2; mt++) {
                const unsigned* pa = Ts + (wm * 32 + mt * 16 + g) * 132 + kkA;
                af[mt][0] = pa[0];
                af[mt][1] = pa[8 * 132];
                af[mt][2] = pa[4];
                af[mt][3] = pa[8 * 132 + 4];
            }
            const unsigned* pb = XB + (ks * 8 + t) * 136 + wn * 64 + g;
            unsigned bf[8][2];
#pragma unroll
            for (int nt = 0; nt < 8; nt++) {
                bf[nt][0] = pb[nt * 8];
                bf[nt][1] = pb[4 * 136 + nt * 8];
            }
#pragma unroll
            for (int mt = 0; mt < 2; mt++)
#pragma unroll
                for (int nt = 0; nt < 8; nt++)
                    mma_tf32(C[mt][nt], af[mt], bf[nt]);
        }
        if (ch < 3) {
            unsigned* XN = Xs + ((ch + 1) & 1) * 4352;
#pragma unroll
            for (int i2 = 0; i2 < 4; i2++) {
                uint4 v = make_uint4(f2tf(st[i2].x), f2tf(st[i2].y),
                                     f2tf(st[i2].z), f2tf(st[i2].w));
                *(uint4*)(XN + (sr0 + 8 * i2) * 136 + 4 * hq) = v;
            }
        }
        __syncthreads();
    }

    // ---- epilogue: partial write + last-block reduce + d*xn + GELU ----
    size_t rowbase = (size_t)(b * LSEQ) + t0;
    unsigned cidx = (unsigned)((b * 4 + hT) * 8 + tT);   // 128 distinct tiles
    bool reducer;
    if (tT == 0) {
        reducer = true;
    } else {
        float* P = g_part[sT] + rowbase * H + h0;
#pragma unroll
        for (int mt = 0; mt < 2; mt++) {
            int rr = wm * 32 + mt * 16 + g;
#pragma unroll
            for (int nt = 0; nt < 8; nt++) {
                int cc = wn * 64 + nt * 8 + t * 2;
                *(float2*)(P + (size_t)rr * H + cc)       = make_float2(C[mt][nt][0], C[mt][nt][1]);
                *(float2*)(P + (size_t)(rr + 8) * H + cc) = make_float2(C[mt][nt][2], C[mt][nt][3]);
            }
        }
        __syncthreads();
        if (tid == 0) { __threadfence(); s_last = atomicAdd(&g_cnt[cidx], 1u); }
        __syncthreads();
        reducer = (s_last == (unsigned)tT);
        if (reducer) __threadfence();
    }
    if (reducer) {
        float dv = dscale[0];
#pragma unroll
        for (int mt = 0; mt < 2; mt++) {
            int rr = wm * 32 + mt * 16 + g;
#pragma unroll
            for (int hh = 0; hh < 2; hh++) {
                int row = rr + hh * 8;
                size_t off = (rowbase + row) * H + h0;
#pragma unroll
                for (int nt = 0; nt < 8; nt++) {
                    int cc = wn * 64 + nt * 8 + t * 2;
                    float2 sum = make_float2(0.f, 0.f);
                    for (int s2 = 0; s2 <= tT; s2++) {
                        if (s2 == sT) {
                            sum.x += C[mt][nt][hh * 2];
                            sum.y += C[mt][nt][hh * 2 + 1];
                        } else {
                            float2 p = __ldcg((const float2*)(g_part[s2] + off + cc));
                            sum.x += p.x; sum.y += p.y;
                        }
                    }
                    float2 xn2 = *(const float2*)(g_xn + off + cc);
                    float y0 = sum.x + dv * xn2.x;
                    float y1 = sum.y + dv * xn2.y;
                    *(float2*)(g_yg + off + cc) = make_float2(gelu1(y0), gelu1(y1));
                }
            }
        }
        if (tT > 0 && tid == 0) g_cnt[cidx] = 0;   // clean for next replay
    }
}

// ================= dual GEMM on tensor cores (tf32 mma.sync) =================
#define GM_SMEM_BYTES (2 * 2 * 4608 * 4)

__global__ void __launch_bounds__(256) k_gemm(
    const float* __restrict__ W1, const float* __restrict__ W2,
    const float* __restrict__ b1, const float* __restrict__ b2,
    const float* __restrict__ skip, float* __restrict__ out) {
    extern __shared__ unsigned sh[];
    int r0 = blockIdx.x * 128, o0 = blockIdx.y * 64;
    int tid = threadIdx.x;
    int lane = tid & 31, warp = tid >> 5;
    int g = lane >> 2, t = lane & 3;
    int wm = warp & 1, wn = warp >> 1;

    int lrow = tid >> 1, lseg = tid & 1;
    const float* Asrc = g_yg + (size_t)(r0 + lrow) * H + lseg * 16;
    int sub = lrow & 15;
    int outn = o0 + (lrow >> 4) * 8 + (sub & 7);
    const float* Bsrc = ((sub < 8) ? W1 : W2) + (size_t)outn * H + lseg * 16;
    unsigned woff = lrow * 36 + lseg * 16;

    float C[4][4][4];
#pragma unroll
    for (int a = 0; a < 4; a++)
#pragma unroll
        for (int b = 0; b < 4; b++)
#pragma unroll
            for (int c = 0; c < 4; c++) C[a][b][c] = 0.f;

#pragma unroll
    for (int q = 0; q < 4; q++) {
        float4 va = *(const float4*)(Asrc + q * 4);
        uint4 ua = make_uint4(f2tf(va.x), f2tf(va.y), f2tf(va.z), f2tf(va.w));
        *(uint4*)&sh[woff + q * 4] = ua;
        float4 vb = *(const float4*)(Bsrc + q * 4);
        uint4 ub = make_uint4(f2tf(vb.x), f2tf(vb.y), f2tf(vb.z), f2tf(vb.w));
        *(uint4*)&sh[4608 + woff + q * 4] = ub;
    }
    __syncthreads();

    for (int ch = 0; ch < 16; ch++) {
        float4 stA[4], stB[4];
        if (ch < 15) {
            const float* pa = Asrc + (ch + 1) * 32;
            const float* pb = Bsrc + (ch + 1) * 32;
#pragma unroll
            for (int q = 0; q < 4; q++) { stA[q] = *(const float4*)(pa + q * 4);
                                          stB[q] = *(const float4*)(pb + q * 4); }
        }
        const unsigned* A = sh + (ch & 1) * 9216;
        const unsigned* B = A + 4608;
#pragma unroll
        for (int ks = 0; ks < 4; ks++) {
            int kk = ks * 8 + t;
            unsigned af[4][4], bf[4][2];
#pragma unroll
            for (int mt = 0; mt < 4; mt++) {
                const unsigned* p = A + (wm * 64 + mt * 16 + g) * 36 + kk;
                af[mt][0] = p[0]; af[mt][1] = p[8 * 36];
                af[mt][2] = p[4]; af[mt][3] = p[8 * 36 + 4];
            }
#pragma unroll
            for (int nt = 0; nt < 4; nt++) {
                const unsigned* p = B + (wn * 32 + nt * 8 + g) * 36 + kk;
                bf[nt][0] = p[0]; bf[nt][1] = p[4];
            }
#pragma unroll
            for (int mt = 0; mt < 4; mt++)
#pragma unroll
                for (int nt = 0; nt < 4; nt++)
                    mma_tf32(C[mt][nt], af[mt], bf[nt]);
        }
        if (ch < 15) {
            unsigned* dA = sh + ((ch + 1) & 1) * 9216 + woff;
            unsigned* dB = dA + 4608;
#pragma unroll
            for (int q = 0; q < 4; q++) {
                *(uint4*)(dA + q * 4) = make_uint4(f2tf(stA[q].x), f2tf(stA[q].y),
                                                   f2tf(stA[q].z), f2tf(stA[q].w));
                *(uint4*)(dB + q * 4) = make_uint4(f2tf(stB[q].x), f2tf(stB[q].y),
                                                   f2tf(stB[q].z), f2tf(stB[q].w));
            }
        }
        __syncthreads();
    }

    float b1v[2][2], b2v[2][2];
#pragma unroll
    for (int p = 0; p < 2; p++) {
        int col = o0 + wn * 16 + p * 8 + t * 2;
        b1v[p][0] = b1[col]; b1v[p][1] = b1[col + 1];
        b2v[p][0] = b2[col]; b2v[p][1] = b2[col + 1];
    }
#pragma unroll
    for (int mt = 0; mt < 4; mt++) {
        int row = r0 + wm * 64 + mt * 16 + g;
#pragma unroll
        for (int p = 0; p < 2; p++) {
            int col = o0 + wn * 16 + p * 8 + t * 2;
            const float* pr = C[mt][2 * p];
            const float* ga = C[mt][2 * p + 1];
#pragma unroll
            for (int h = 0; h < 2; h++) {
                int rw = row + h * 8;
                float v0 = pr[h * 2 + 0] + b1v[p][0];
                float v1 = pr[h * 2 + 1] + b1v[p][1];
                float g0 = ga[h * 2 + 0] + b2v[p][0];
                float g1 = ga[h * 2 + 1] + b2v[p][1];
                float o0v = skip[(size_t)rw * H + col]     + v0 / (1.f + __expf(-g0));
                float o1v = skip[(size_t)rw * H + col + 1] + v1 / (1.f + __expf(-g1));
                *(float2*)(out + (size_t)rw * H + col) = make_float2(o0v, o1v);
            }
        }
    }
}

extern "C" void kernel_launch(void* const* d_in, const int* in_sizes, int n_in,
                              void* d_out, int out_size) {
    const float* x   = (const float*)d_in[0];
    const float* nw  = (const float*)d_in[1];
    const float* nb  = (const float*)d_in[2];
    const float* lre = (const float*)d_in[3];
    const float* lim = (const float*)d_in[4];
    const float* pre = (const float*)d_in[5];
    const float* pim = (const float*)d_in[6];
    const float* bre = (const float*)d_in[7];
    const float* bim = (const float*)d_in[8];
    const float* cre = (const float*)d_in[9];
    const float* cim = (const float*)d_in[10];
    const float* dd  = (const float*)d_in[11];
    const float* ls  = (const float*)d_in[12];
    const float* W1  = (const float*)d_in[13];
    const float* b1  = (const float*)d_in[14];
    const float* W2  = (const float*)d_in[15];
    const float* b2  = (const float*)d_in[16];
    float* out = (float*)d_out;

    size_t kt_smem = (size_t)KT_SMEM_F2 * sizeof(float2);
    cudaFuncSetAttribute(k_ktail_ln, cudaFuncAttributeMaxDynamicSharedMemorySize, (int)kt_smem);
    cudaFuncSetAttribute(k_gemm, cudaFuncAttributeMaxDynamicSharedMemorySize, GM_SMEM_BYTES);
    cudaFuncSetAttribute(k_conv, cudaFuncAttributeMaxDynamicSharedMemorySize, CONV_SMEM);

    k_sq0<<<65, 256>>>(lre, lim, pre, pim, bre, bim, ls);
    for (int ph = 1; ph < 6; ph++)
        k_sqN<<<64 + (1 << ph), 256>>>(ph);
    k_ktail_ln<<<513, 1024, kt_smem>>>(cre, cim, x, nw, nb);
    k_conv<<<576, 256, CONV_SMEM>>>(dd);
    k_gemm<<<dim3(32, 8), 256, GM_SMEM_BYTES>>>(W1, W2, b1, b2, x, out);
}

// round 17
// speedup vs baseline: 1.4651x; 1.4651x over previous
#include <cuda_runtime.h>

#define H 512
#define LSEQ 1024
#define NROWS 4096
#define NST 64

typedef unsigned long long u64;

// ---- complex helpers ----
__device__ __forceinline__ float2 cmul(float2 a, float2 b) {
    return make_float2(a.x*b.x - a.y*b.y, a.x*b.y + a.y*b.x);
}
__device__ __forceinline__ float2 cadd(float2 a, float2 b) { return make_float2(a.x+b.x, a.y+b.y); }
__device__ __forceinline__ float2 csub(float2 a, float2 b) { return make_float2(a.x-b.x, a.y-b.y); }
__device__ __forceinline__ float2 cscale(float2 a, float s) { return make_float2(a.x*s, a.y*s); }
__device__ __forceinline__ float2 cinv(float2 d) {
    float inv = 1.f / (d.x*d.x + d.y*d.y);
    return make_float2(d.x*inv, -d.y*inv);
}

// ---- tf32 ----
__device__ __forceinline__ unsigned f2tf(float x) {
    unsigned u; asm("cvt.rna.tf32.f32 %0,%1;" : "=r"(u) : "f"(x)); return u;
}
__device__ __forceinline__ void mma_tf32(float* c, const unsigned* a, const unsigned* b) {
    asm("mma.sync.aligned.m16n8k8.row.col.f32.tf32.tf32.f32 "
        "{%0,%1,%2,%3}, {%4,%5,%6,%7}, {%8,%9}, {%0,%1,%2,%3};"
        : "+f"(c[0]), "+f"(c[1]), "+f"(c[2]), "+f"(c[3])
        : "r"(a[0]), "r"(a[1]), "r"(a[2]), "r"(a[3]), "r"(b[0]), "r"(b[1]));
}

// ---- scratch ----
__device__ float  g_xn[NROWS * H];
__device__ float  g_yg[NROWS * H];
__device__ float  g_part[8][NROWS * H];
__device__ float2 g_M[2][NST * NST];
__device__ float2 g_MT[2][NST * NST];
__device__ float2 g_S[NST * NST];
__device__ float  g_K[LSEQ];

// ---- reduce over threads 0..63 (others pass zero; all 256 call) ----
__device__ __forceinline__ float2 reduce64b(float2 val, float2* red) {
    int t = threadIdx.x;
#pragma unroll
    for (int o = 16; o > 0; o >>= 1) {
        val.x += __shfl_down_sync(0xffffffffu, val.x, o);
        val.y += __shfl_down_sync(0xffffffffu, val.y, o);
    }
    if (t < 64 && (t & 31) == 0) red[t >> 5] = val;
    __syncthreads();
    float2 r = cadd(red[0], red[1]);
    __syncthreads();
    return r;
}

// ================= sq0: setup + first squaring + s0/s1, plus LN ride-along =================
// blocks 0..63: Ab^2 rows -> g_M[0]/g_MT[0]; block 64: s0,s1 -> g_S;
// blocks 65..2112: LayerNorm, 2 rows each (static smem only ~37KB -> 6 blocks/SM).
__global__ void __launch_bounds__(256) k_sq0(
    const float* lre, const float* lim, const float* pre, const float* pim,
    const float* bre, const float* bim, const float* logstep,
    const float* __restrict__ x, const float* __restrict__ w,
    const float* __restrict__ bi) {
    __shared__ float2 AbS[NST * 65];
    __shared__ float2 su[NST], sv[NST], sg[NST], ss0[NST];
    __shared__ float2 vec[NST];
    __shared__ float2 part[3][NST];
    __shared__ float2 red[2];
    int tid = threadIdx.x, blk = blockIdx.x;
    const float2 zero = make_float2(0.f, 0.f);

    if (blk >= 65) {
        // ---- LayerNorm: 2 rows per block, 128 threads per row ----
        __shared__ float rs2[2][4], rss2[2][4];
        int grp = tid >> 7;
        int t = tid & 127;
        int row = (blk - 65) * 2 + grp;
        float4 v = ((const float4*)(x + (size_t)row * H))[t];
        float s  = v.x + v.y + v.z + v.w;
        float ss = v.x*v.x + v.y*v.y + v.z*v.z + v.w*v.w;
#pragma unroll
        for (int o = 16; o > 0; o >>= 1) {
            s  += __shfl_down_sync(0xffffffffu, s, o);
            ss += __shfl_down_sync(0xffffffffu, ss, o);
        }
        if ((t & 31) == 0) { rs2[grp][t >> 5] = s; rss2[grp][t >> 5] = ss; }
        __syncthreads();
        float sum = rs2[grp][0] + rs2[grp][1] + rs2[grp][2] + rs2[grp][3];
        float sq  = rss2[grp][0] + rss2[grp][1] + rss2[grp][2] + rss2[grp][3];
        float mu = sum * (1.f / H);
        float var = sq * (1.f / H) - mu * mu;
        float rstd = rsqrtf(var + 1e-5f);
        float4 wv = ((const float4*)w)[t];
        float4 bv = ((const float4*)bi)[t];
        float4 o;
        o.x = (v.x - mu) * rstd * wv.x + bv.x;
        o.y = (v.y - mu) * rstd * wv.y + bv.y;
        o.z = (v.z - mu) * rstd * wv.z + bv.z;
        o.w = (v.w - mu) * rstd * wv.w + bv.w;
        ((float4*)(g_xn + (size_t)row * H))[t] = o;
        return;
    }

    // ---- setup (redundant per K-block) ----
    {
        float dt = expf(logstep[0]);
        float w0 = 2.f / dt;
        float2 lam = zero, p = zero, bb = zero, Dl = zero, d0 = zero, sp = zero;
        if (tid < NST) {
            lam = make_float2(lre[tid], lim[tid]);
            p   = make_float2(pre[tid], pim[tid]);
            bb  = make_float2(bre[tid], bim[tid]);
            Dl  = cinv(make_float2(w0 - lam.x, -lam.y));
            d0  = make_float2(w0 + lam.x, lam.y);
            sp  = cscale(Dl, p.x*p.x + p.y*p.y);
        }
        float2 sig = reduce64b(sp, red);
        float2 Db = zero, tp = zero;
        if (tid < NST) {
            Db = cmul(Dl, bb);
            tp = cmul(make_float2(p.x, -p.y), Db);
        }
        float2 tau = reduce64b(tp, red);
        if (tid < NST) {
            float2 alpha = cinv(make_float2(1.f + sig.x, sig.y));
            float2 uu = cmul(Dl, p);
            float2 gg = cmul(Dl, d0);
            float2 as = cmul(alpha, sig);
            float2 coef = csub(make_float2(as.x - 1.f, as.y), cmul(alpha, gg));
            float2 vv = cmul(make_float2(p.x, -p.y), coef);
            float2 Bv = cscale(csub(Db, cmul(cmul(alpha, tau), uu)), 2.f);
            su[tid] = uu; sv[tid] = vv; sg[tid] = gg; ss0[tid] = Bv;
        }
        __syncthreads();
        for (int idx = tid; idx < 4096; idx += 256) {
            int i = idx >> 6, j = idx & 63;
            float2 e = cmul(su[i], sv[j]);
            if (i == j) e = cadd(e, sg[i]);
            AbS[i * 65 + j] = e;
        }
        __syncthreads();
    }

    if (blk < 64) {
        if (tid < NST) vec[tid] = AbS[blk * 65 + tid];
        __syncthreads();
        int j = tid & 63, q = tid >> 6;
        float2 acc = zero;
#pragma unroll
        for (int nn = 0; nn < 16; nn++) {
            int n = q * 16 + nn;
            acc = cadd(acc, cmul(vec[n], AbS[n * 65 + j]));
        }
        if (q) part[q - 1][j] = acc;
        __syncthreads();
        if (q == 0) {
            acc = cadd(acc, cadd(part[0][j], cadd(part[1][j], part[2][j])));
            g_M[0][blk * NST + j] = acc;
            g_MT[0][j * NST + blk] = acc;
        }
    } else {
        float2 dp = zero;
        if (tid < NST) dp = cmul(sv[tid], ss0[tid]);
        float2 dot = reduce64b(dp, red);
        if (tid < NST) {
            g_S[tid] = ss0[tid];
            g_S[NST + tid] = cadd(cmul(sg[tid], ss0[tid]), cmul(su[tid], dot));
        }
    }
}

// ================= sqN: phase ph in 1..5 (grid 64 + 2^ph), round-11 body =================
__global__ void __launch_bounds__(256) k_sqN(int ph) {
    const float2* Min  = g_M[(ph + 1) & 1];
    const float2* MinT = g_MT[(ph + 1) & 1];
    float2* Mout  = g_M[ph & 1];
    float2* MoutT = g_MT[ph & 1];
    __shared__ float2 vec[NST];
    __shared__ float2 part[3][NST];
    int blk = blockIdx.x, tid = threadIdx.x;
    int j = tid & 63, q = tid >> 6;
    const float2 zero = make_float2(0.f, 0.f);
    if (blk < 64) {
        if (tid < NST) vec[tid] = Min[blk * NST + tid];
        __syncthreads();
        float2 acc = zero;
#pragma unroll
        for (int nn = 0; nn < 16; nn++) {
            int n = q * 16 + nn;
            acc = cadd(acc, cmul(vec[n], Min[n * NST + j]));
        }
        if (q) part[q - 1][j] = acc;
        __syncthreads();
        if (q == 0) {
            acc = cadd(acc, cadd(part[0][j], cadd(part[1][j], part[2][j])));
            Mout[blk * NST + j] = acc;
            MoutT[j * NST + blk] = acc;
        }
    } else {
        int r = 1 << ph;
        int k = blk - 64;
        if (tid < NST) vec[tid] = g_S[k * NST + tid];
        __syncthreads();
        float2 acc = zero;
#pragma unroll
        for (int nn = 0; nn < 16; nn++) {
            int n = q * 16 + nn;
            acc = cadd(acc, cmul(vec[n], MinT[n * NST + j]));
        }
        if (q) part[q - 1][j] = acc;
        __syncthreads();
        if (q == 0) {
            acc = cadd(acc, cadd(part[0][j], cadd(part[1][j], part[2][j])));
            g_S[(k + r) * NST + j] = acc;
        }
    }
}

// ================= K tail: r-chain + cross product (1 block, 1024 thr) =================
#define KT_SMEM_F2 (4160 + 4160 + 1024 + 64 + 64)
__global__ void __launch_bounds__(1024, 1) k_ktail(const float* cre, const float* cim) {
    extern __shared__ float2 sm[];
    float2* ST = sm;
    float2* Ms = ST + 4160;
    float2* Rm = Ms + 4160;
    float2* Rc = Rm + 1024;
    float2* Rn = Rc + 64;
    int tid = threadIdx.x;
    const float2 zero = make_float2(0.f, 0.f);
    for (int e = tid; e < NST * NST; e += 1024) {
        int k = e >> 6, n = e & 63;
        ST[n * 65 + k] = g_S[e];
        Ms[k * 65 + n] = g_M[1][e];   // Ab^64 (phase-5 output)
    }
    if (tid < NST) Rc[tid] = make_float2(cre[tid], cim[tid]);
    __syncthreads();
    int i = tid >> 4, q = tid & 15;
    for (int m = 0; m < 16; m++) {
        if (tid < NST) Rm[m * NST + tid] = Rc[tid];
        float2 acc = zero;
#pragma unroll
        for (int nn = 0; nn < 4; nn++) {
            int n = q * 4 + nn;
            acc = cadd(acc, cmul(Rc[n], Ms[n * 65 + i]));
        }
#pragma unroll
        for (int o = 8; o > 0; o >>= 1) {
            acc.x += __shfl_down_sync(0xffffffffu, acc.x, o, 16);
            acc.y += __shfl_down_sync(0xffffffffu, acc.y, o, 16);
        }
        if (q == 0) Rn[i] = acc;
        __syncthreads();
        if (tid < NST) Rc[tid] = Rn[tid];
        __syncthreads();
    }
    int m = tid >> 6, k = tid & 63;
    float acc = 0.f;
#pragma unroll 8
    for (int n = 0; n < NST; n++) {
        float2 a = Rm[m * NST + n];
        float2 s = ST[n * 65 + k];
        acc += a.x * s.x - a.y * s.y;
    }
    g_K[m * NST + k] = acc;
}

// ================= conv on tensor cores (tf32): Toeplitz A-tile =================
#define CONV_SMEM 103488

__global__ void __launch_bounds__(256) k_conv() {
    extern __shared__ char cvs[];
    float* Ks = (float*)cvs;
    unsigned* Ts = (unsigned*)(cvs + 1088);
    unsigned* Xs = (unsigned*)(cvs + 68672);

    int idx = blockIdx.x;
    int b = idx / 144;
    int rem = idx - b * 144;
    int hT = rem / 36;
    int pr = rem - hT * 36;
    int tT = 0;
    while ((tT + 1) * (tT + 2) / 2 <= pr) tT++;
    int sT = pr - tT * (tT + 1) / 2;
    int t0 = tT * 128, s0 = sT * 128, h0 = hT * 128;
    int D0 = t0 - s0;

    int tid = threadIdx.x;
    int lane = tid & 31, warp = tid >> 5;
    int g = lane >> 2, t = lane & 3;
    int wm = warp & 3, wn = warp >> 2;

    for (int jj = tid; jj < 264; jj += 256) {
        int d = D0 + jj - 131;
        Ks[jj] = (d >= 0 && d < LSEQ) ? g_K[d] : 0.f;
    }
    __syncthreads();

    {
        int tt = tid >> 1, sbase = (tid & 1) * 64;
        const float* kp = Ks + 131 + tt - sbase;
        unsigned* dst = Ts + tt * 132 + sbase;
#pragma unroll
        for (int s = 0; s < 64; s += 4) {
            uint4 v = make_uint4(f2tf(kp[-s]), f2tf(kp[-s - 1]),
                                 f2tf(kp[-s - 2]), f2tf(kp[-s - 3]));
            *(uint4*)(dst + s) = v;
        }
    }

    int hq = tid & 31, sr0 = tid >> 5;
    const float* Xg = g_xn + (size_t)(b * LSEQ + s0) * H + h0 + 4 * hq;
    float4 st[4];
#pragma unroll
    for (int i2 = 0; i2 < 4; i2++) st[i2] = *(const float4*)(Xg + (size_t)(sr0 + 8 * i2) * H);
#pragma unroll
    for (int i2 = 0; i2 < 4; i2++) {
        uint4 v = make_uint4(f2tf(st[i2].x), f2tf(st[i2].y), f2tf(st[i2].z), f2tf(st[i2].w));
        *(uint4*)(Xs + (sr0 + 8 * i2) * 136 + 4 * hq) = v;
    }
    __syncthreads();

    float C[2][8][4];
#pragma unroll
    for (int a = 0; a < 2; a++)
#pragma unroll
        for (int nb = 0; nb < 8; nb++)
#pragma unroll
            for (int cc = 0; cc < 4; cc++) C[a][nb][cc] = 0.f;

    for (int ch = 0; ch < 4; ch++) {
        if (ch < 3) {
#pragma unroll
            for (int i2 = 0; i2 < 4; i2++)
                st[i2] = *(const float4*)(Xg + (size_t)((ch + 1) * 32 + sr0 + 8 * i2) * H);
        }
        const unsigned* XB = Xs + (ch & 1) * 4352;
#pragma unroll
        for (int ks = 0; ks < 4; ks++) {
            int kkA = ch * 32 + ks * 8 + t;
            unsigned af[2][4];
#pragma unroll
            for (int mt = 0; mt < 2; mt++) {
                const unsigned* pa = Ts + (wm * 32 + mt * 16 + g) * 132 + kkA;
                af[mt][0] = pa[0];
                af[mt][1] = pa[8 * 132];
                af[mt][2] = pa[4];
                af[mt][3] = pa[8 * 132 + 4];
            }
            const unsigned* pb = XB + (ks * 8 + t) * 136 + wn * 64 + g;
            unsigned bf[8][2];
#pragma unroll
            for (int nt = 0; nt < 8; nt++) {
                bf[nt][0] = pb[nt * 8];
                bf[nt][1] = pb[4 * 136 + nt * 8];
            }
#pragma unroll
            for (int mt = 0; mt < 2; mt++)
#pragma unroll
                for (int nt = 0; nt < 8; nt++)
                    mma_tf32(C[mt][nt], af[mt], bf[nt]);
        }
        if (ch < 3) {
            unsigned* XN = Xs + ((ch + 1) & 1) * 4352;
#pragma unroll
            for (int i2 = 0; i2 < 4; i2++) {
                uint4 v = make_uint4(f2tf(st[i2].x), f2tf(st[i2].y),
                                     f2tf(st[i2].z), f2tf(st[i2].w));
                *(uint4*)(XN + (sr0 + 8 * i2) * 136 + 4 * hq) = v;
            }
        }
        __syncthreads();
    }

    float* P = g_part[sT] + ((size_t)(b * LSEQ) + t0) * H + h0;
#pragma unroll
    for (int mt = 0; mt < 2; mt++) {
        int rr = wm * 32 + mt * 16 + g;
#pragma unroll
        for (int nt = 0; nt < 8; nt++) {
            int cc = wn * 64 + nt * 8 + t * 2;
            *(float2*)(P + (size_t)rr * H + cc)       = make_float2(C[mt][nt][0], C[mt][nt][1]);
            *(float2*)(P + (size_t)(rr + 8) * H + cc) = make_float2(C[mt][nt][2], C[mt][nt][3]);
        }
    }
}

// ================= split reduce + d*xn + GELU =================
__global__ void k_gelu(const float* __restrict__ dscale) {
    int idx = blockIdx.x * 256 + threadIdx.x;
    int row = idx >> 7, c4 = idx & 127;
    int t = row & (LSEQ - 1);
    int tT = t >> 7;
    size_t off = (size_t)row * H + c4 * 4;
    float4 s = make_float4(0.f, 0.f, 0.f, 0.f);
    for (int j = 0; j <= tT; j++) {
        float4 p = *(const float4*)(g_part[j] + off);
        s.x += p.x; s.y += p.y; s.z += p.z; s.w += p.w;
    }
    float dv = dscale[0];
    float4 xn = *(const float4*)(g_xn + off);
    float y0 = s.x + dv * xn.x, y1 = s.y + dv * xn.y;
    float y2 = s.z + dv * xn.z, y3 = s.w + dv * xn.w;
    float4 o;
    float z;
    z = 0.7978845608f * (y0 + 0.044715f * y0 * y0 * y0); o.x = y0 / (1.f + __expf(-2.f * z));
    z = 0.7978845608f * (y1 + 0.044715f * y1 * y1 * y1); o.y = y1 / (1.f + __expf(-2.f * z));
    z = 0.7978845608f * (y2 + 0.044715f * y2 * y2 * y2); o.z = y2 / (1.f + __expf(-2.f * z));
    z = 0.7978845608f * (y3 + 0.044715f * y3 * y3 * y3); o.w = y3 / (1.f + __expf(-2.f * z));
    *(float4*)(g_yg + off) = o;
}

// ================= dual GEMM on tensor cores (tf32 mma.sync) =================
#define GM_SMEM_BYTES (2 * 2 * 4608 * 4)

__global__ void __launch_bounds__(256) k_gemm(
    const float* __restrict__ W1, const float* __restrict__ W2,
    const float* __restrict__ b1, const float* __restrict__ b2,
    const float* __restrict__ skip, float* __restrict__ out) {
    extern __shared__ unsigned sh[];
    int r0 = blockIdx.x * 128, o0 = blockIdx.y * 64;
    int tid = threadIdx.x;
    int lane = tid & 31, warp = tid >> 5;
    int g = lane >> 2, t = lane & 3;
    int wm = warp & 1, wn = warp >> 1;

    int lrow = tid >> 1, lseg = tid & 1;
    const float* Asrc = g_yg + (size_t)(r0 + lrow) * H + lseg * 16;
    int sub = lrow & 15;
    int outn = o0 + (lrow >> 4) * 8 + (sub & 7);
    const float* Bsrc = ((sub < 8) ? W1 : W2) + (size_t)outn * H + lseg * 16;
    unsigned woff = lrow * 36 + lseg * 16;

    float C[4][4][4];
#pragma unroll
    for (int a = 0; a < 4; a++)
#pragma unroll
        for (int b = 0; b < 4; b++)
#pragma unroll
            for (int c = 0; c < 4; c++) C[a][b][c] = 0.f;

#pragma unroll
    for (int q = 0; q < 4; q++) {
        float4 va = *(const float4*)(Asrc + q * 4);
        uint4 ua = make_uint4(f2tf(va.x), f2tf(va.y), f2tf(va.z), f2tf(va.w));
        *(uint4*)&sh[woff + q * 4] = ua;
        float4 vb = *(const float4*)(Bsrc + q * 4);
        uint4 ub = make_uint4(f2tf(vb.x), f2tf(vb.y), f2tf(vb.z), f2tf(vb.w));
        *(uint4*)&sh[4608 + woff + q * 4] = ub;
    }
    __syncthreads();

    for (int ch = 0; ch < 16; ch++) {
        float4 stA[4], stB[4];
        if (ch < 15) {
            const float* pa = Asrc + (ch + 1) * 32;
            const float* pb = Bsrc + (ch + 1) * 32;
#pragma unroll
            for (int q = 0; q < 4; q++) { stA[q] = *(const float4*)(pa + q * 4);
                                          stB[q] = *(const float4*)(pb + q * 4); }
        }
        const unsigned* A = sh + (ch & 1) * 9216;
        const unsigned* B = A + 4608;
#pragma unroll
        for (int ks = 0; ks < 4; ks++) {
            int kk = ks * 8 + t;
            unsigned af[4][4], bf[4][2];
#pragma unroll
            for (int mt = 0; mt < 4; mt++) {
                const unsigned* p = A + (wm * 64 + mt * 16 + g) * 36 + kk;
                af[mt][0] = p[0]; af[mt][1] = p[8 * 36];
                af[mt][2] = p[4]; af[mt][3] = p[8 * 36 + 4];
            }
#pragma unroll
            for (int nt = 0; nt < 4; nt++) {
                const unsigned* p = B + (wn * 32 + nt * 8 + g) * 36 + kk;
                bf[nt][0] = p[0]; bf[nt][1] = p[4];
            }
#pragma unroll
            for (int mt = 0; mt < 4; mt++)
#pragma unroll
                for (int nt = 0; nt < 4; nt++)
                    mma_tf32(C[mt][nt], af[mt], bf[nt]);
        }
        if (ch < 15) {
            unsigned* dA = sh + ((ch + 1) & 1) * 9216 + woff;
            unsigned* dB = dA + 4608;
#pragma unroll
            for (int q = 0; q < 4; q++) {
                *(uint4*)(dA + q * 4) = make_uint4(f2tf(stA[q].x), f2tf(stA[q].y),
                                                   f2tf(stA[q].z), f2tf(stA[q].w));
                *(uint4*)(dB + q * 4) = make_uint4(f2tf(stB[q].x), f2tf(stB[q].y),
                                                   f2tf(stB[q].z), f2tf(stB[q].w));
            }
        }
        __syncthreads();
    }

    float b1v[2][2], b2v[2][2];
#pragma unroll
    for (int p = 0; p < 2; p++) {
        int col = o0 + wn * 16 + p * 8 + t * 2;
        b1v[p][0] = b1[col]; b1v[p][1] = b1[col + 1];
        b2v[p][0] = b2[col]; b2v[p][1] = b2[col + 1];
    }
#pragma unroll
    for (int mt = 0; mt < 4; mt++) {
        int row = r0 + wm * 64 + mt * 16 + g;
#pragma unroll
        for (int p = 0; p < 2; p++) {
            int col = o0 + wn * 16 + p * 8 + t * 2;
            const float* pr = C[mt][2 * p];
            const float* ga = C[mt][2 * p + 1];
#pragma unroll
            for (int h = 0; h < 2; h++) {
                int rw = row + h * 8;
                float v0 = pr[h * 2 + 0] + b1v[p][0];
                float v1 = pr[h * 2 + 1] + b1v[p][1];
                float g0 = ga[h * 2 + 0] + b2v[p][0];
                float g1 = ga[h * 2 + 1] + b2v[p][1];
                float o0v = skip[(size_t)rw * H + col]     + v0 / (1.f + __expf(-g0));
                float o1v = skip[(size_t)rw * H + col + 1] + v1 / (1.f + __expf(-g1));
                *(float2*)(out + (size_t)rw * H + col) = make_float2(o0v, o1v);
            }
        }
    }
}

extern "C" void kernel_launch(void* const* d_in, const int* in_sizes, int n_in,
                              void* d_out, int out_size) {
    const float* x   = (const float*)d_in[0];
    const float* nw  = (const float*)d_in[1];
    const float* nb  = (const float*)d_in[2];
    const float* lre = (const float*)d_in[3];
    const float* lim = (const float*)d_in[4];
    const float* pre = (const float*)d_in[5];
    const float* pim = (const float*)d_in[6];
    const float* bre = (const float*)d_in[7];
    const float* bim = (const float*)d_in[8];
    const float* cre = (const float*)d_in[9];
    const float* cim = (const float*)d_in[10];
    const float* dd  = (const float*)d_in[11];
    const float* ls  = (const float*)d_in[12];
    const float* W1  = (const float*)d_in[13];
    const float* b1  = (const float*)d_in[14];
    const float* W2  = (const float*)d_in[15];
    const float* b2  = (const float*)d_in[16];
    float* out = (float*)d_out;

    size_t kt_smem = (size_t)KT_SMEM_F2 * sizeof(float2);
    cudaFuncSetAttribute(k_ktail, cudaFuncAttributeMaxDynamicSharedMemorySize, (int)kt_smem);
    cudaFuncSetAttribute(k_gemm, cudaFuncAttributeMaxDynamicSharedMemorySize, GM_SMEM_BYTES);
    cudaFuncSetAttribute(k_conv, cudaFuncAttributeMaxDynamicSharedMemorySize, CONV_SMEM);

    k_sq0<<<65 + 2048, 256>>>(lre, lim, pre, pim, bre, bim, ls, x, nw, nb);
    for (int ph = 1; ph < 6; ph++)
        k_sqN<<<64 + (1 << ph), 256>>>(ph);
    k_ktail<<<1, 1024, kt_smem>>>(cre, cim);
    k_conv<<<576, 256, CONV_SMEM>>>();
    k_gelu<<<2048, 256>>>(dd);
    k_gemm<<<dim3(32, 8), 256, GM_SMEM_BYTES>>>(W1, W2, b1, b2, x, out);
}